// round 6
// baseline (speedup 1.0000x reference)
#include <cuda_runtime.h>

#define NBATCH 2048
#define NVAR   8
#define NTOT   6561          // 3^8
#define NQUAD  1640          // full 4-group (144B) quads; group 6560 is the tail
#define GBLK   128
#define TBLK   128           // 128*128 = 16384 threads; 8 threads per batch element

__device__ float g_Cpart[GBLK * 9];
__device__ float g_Spart[GBLK];
__device__ int   g_ctr;      // monotonic barrier ticket counter (never reset)

__device__ __forceinline__ float rcpa(float v) {
    float r; asm("rcp.approx.f32 %0, %1;" : "=f"(r) : "f"(v)); return r;
}
__device__ __forceinline__ float lg2a(float v) {
    float r; asm("lg2.approx.f32 %0, %1;" : "=f"(r) : "f"(v)); return r;
}
__device__ __forceinline__ float ex2a(float v) {
    float r; asm("ex2.approx.f32 %0, %1;" : "=f"(r) : "f"(v)); return r;
}

// (1 + t), t = ((x-c)/a)^(2b), replicating numpy edge cases:
//   b==0        -> t=1   (0**0 == inf**0 == 1)
//   x2==0, b>0  -> t=0
//   a==0        -> x2=inf -> t=inf (product -> inf -> P=0 via rcp)
__device__ __forceinline__ float one_plus_t(float x, float a, float b, float c) {
    float u  = (x - c) * rcpa(a);
    float x2 = u * u;
    float t;
    if (b == 0.0f)       t = 1.0f;
    else if (x2 == 0.0f) t = 0.0f;
    else                 t = ex2a(b * lg2a(x2));
    return 1.0f + t;
}

__global__ __launch_bounds__(TBLK)
void anfis_fused(const float* __restrict__ inp,
                 const float* __restrict__ prem,
                 const float* __restrict__ conseq,
                 float* __restrict__ out) {
    __shared__ float swC[4][9];      // per-warp conseq partials
    __shared__ float swS[4];         // per-warp S partials
    __shared__ float sF[8][9];       // fold level-1
    __shared__ float sS[8];
    __shared__ float sC[9];
    __shared__ float sInvZ;

    const int tid  = threadIdx.x;
    const int bi   = blockIdx.x;
    const int w    = tid >> 5, lane = tid & 31;
    const int var  = lane >> 2;                    // this thread's variable (0..7)
    const int b    = bi * 16 + w * 4 + (lane & 3); // batch element

    // ---- Issue all global loads up front (MLP overlaps MUFU below) ----
    // Conseq: quads distributed across warps — lanes 28..31 of each warp.
    float4 cv[9];
    const int qidx = w * 4 + (lane - 28);          // 0..15 for lanes 28..31
    const int q    = bi + GBLK * qidx;
    const bool qact = (lane >= 28) && (qidx < 13) && (q < NQUAD);
    if (qact) {
        const float4* p = (const float4*)(conseq + 36 * q);
#pragma unroll
        for (int m = 0; m < 9; m++) cv[m] = __ldg(p + m);
    }

    const float x = __ldg(inp + var * NBATCH + b);
    const float* r = prem + 9 * var;               // rows 3*var .. 3*var+2
    float pp[9];
#pragma unroll
    for (int k = 0; k < 9; k++) pp[k] = __ldg(r + k);

    // ---- Memberships: 1 var x 3 sets per thread ----
    float q0 = one_plus_t(x, pp[0], pp[1], pp[2]);
    float q1 = one_plus_t(x, pp[3], pp[4], pp[5]);
    float q2 = one_plus_t(x, pp[6], pp[7], pp[8]);

    // combine the 8 var-lanes of each element (lane bits 2,3,4)
    q0 *= __shfl_xor_sync(0xffffffffu, q0, 4);
    q1 *= __shfl_xor_sync(0xffffffffu, q1, 4);
    q2 *= __shfl_xor_sync(0xffffffffu, q2, 4);
    q0 *= __shfl_xor_sync(0xffffffffu, q0, 8);
    q1 *= __shfl_xor_sync(0xffffffffu, q1, 8);
    q2 *= __shfl_xor_sync(0xffffffffu, q2, 8);
    q0 *= __shfl_xor_sync(0xffffffffu, q0, 16);
    q1 *= __shfl_xor_sync(0xffffffffu, q1, 16);
    q2 *= __shfl_xor_sync(0xffffffffu, q2, 16);
    const float P0 = rcpa(q0);
    float S = P0 + rcpa(q1) + rcpa(q2);

    // warp S sum: lanes differing in bits 0,1 hold the warp's 4 distinct
    // elements; the 8 var-copies live in bits 2..4 and are NOT summed,
    // so no over-count and no scaling.
    S += __shfl_xor_sync(0xffffffffu, S, 1);
    S += __shfl_xor_sync(0xffffffffu, S, 2);

    // ---- Accumulate conseq quad into Ctot[9] buckets ----
    float acc[9];
#pragma unroll
    for (int v = 0; v < 9; v++) acc[v] = 0.0f;
    if (qact) {
#pragma unroll
        for (int m = 0; m < 9; m++) {
            acc[(4 * m + 0) % 9] += cv[m].x;
            acc[(4 * m + 1) % 9] += cv[m].y;
            acc[(4 * m + 2) % 9] += cv[m].z;
            acc[(4 * m + 3) % 9] += cv[m].w;
        }
    }
    if (bi == GBLK - 1 && tid == TBLK - 1) {       // tail group 6560
#pragma unroll
        for (int k = 0; k < 9; k++) acc[k] += __ldg(conseq + 36 * NQUAD + k);
    }

    // reduce over lanes 28..31 into lane 28 (2 shfl_down steps)
#pragma unroll
    for (int v = 0; v < 9; v++) {
        acc[v] += __shfl_down_sync(0xffffffffu, acc[v], 1);
        acc[v] += __shfl_down_sync(0xffffffffu, acc[v], 2);
    }
    if (lane == 28) {
#pragma unroll
        for (int v = 0; v < 9; v++) swC[w][v] = acc[v];
    }
    if (lane == 0) swS[w] = S;
    __syncthreads();

    // ---- Parallel publish of this block's partials ----
    if (tid < 9)
        g_Cpart[bi * 9 + tid] = swC[0][tid] + swC[1][tid] + swC[2][tid] + swC[3][tid];
    if (tid == 9)
        g_Spart[bi] = swS[0] + swS[1] + swS[2] + swS[3];
    __syncthreads();

    // ---- Grid barrier (monotonic ticket, graph-replay safe) ----
    if (tid == 0) {
        __threadfence();                           // publishes -> L2 before ticket
        int ticket = atomicAdd(&g_ctr, 1);
        int target = (ticket / GBLK + 1) * GBLK;
        volatile int* vp = &g_ctr;
        while (*vp < target) { }
    }
    __syncthreads();

    // ---- Two-level fold of partials (L2 reads, bypass L1) ----
    if (tid < 72) {                                // 8 parts x 9 buckets
        const int v = tid % 9, part = tid / 9;
        float s = 0.0f;
#pragma unroll
        for (int k = 0; k < GBLK / 8; k++)
            s += __ldcg(&g_Cpart[(part * (GBLK / 8) + k) * 9 + v]);
        sF[part][v] = s;
    }
    if (tid >= 72 && tid < 80) {                   // 8 parts of S
        const int part = tid - 72;
        float s = 0.0f;
#pragma unroll
        for (int k = 0; k < GBLK / 8; k++)
            s += __ldcg(&g_Spart[part * (GBLK / 8) + k]);
        sS[part] = s;
    }
    __syncthreads();
    if (tid < 9) {
        float s = 0.0f;
#pragma unroll
        for (int p = 0; p < 8; p++) s += sF[p][tid];
        sC[tid] = s;
    }
    if (tid == 9) {
        float s = 0.0f;
#pragma unroll
        for (int p = 0; p < 8; p++) s += sS[p];
        sInvZ = 1.0f / (2187.0f * s);              // Z = 2187 * sum_b (P0+P1+P2)
    }
    __syncthreads();

    // ---- Finalize: dot via butterfly over the 8 var-lanes ----
    float d = x * sC[var];
    d += __shfl_xor_sync(0xffffffffu, d, 4);
    d += __shfl_xor_sync(0xffffffffu, d, 8);
    d += __shfl_xor_sync(0xffffffffu, d, 16);
    if (var == 0)
        out[b] = P0 * (d + sC[8]) * sInvZ;
}

extern "C" void kernel_launch(void* const* d_in, const int* in_sizes, int n_in,
                              void* d_out, int out_size) {
    const float* inp    = (const float*)d_in[0];   // (8, 2048)
    const float* prem   = (const float*)d_in[1];   // (24, 3)
    const float* conseq = (const float*)d_in[2];   // (59049, 1)
    float* out = (float*)d_out;                    // (2048, 1)

    anfis_fused<<<GBLK, TBLK>>>(inp, prem, conseq, out);
}

// round 7
// speedup vs baseline: 1.1857x; 1.1857x over previous
#include <cuda_runtime.h>

#define NBATCH 2048
#define NVAR   8
#define NTOT   6561          // 3^8
#define NQUAD  1640          // full 4-group (144B) quads; group 6560 is the tail
#define GBLK   64
#define TBLK   128           // 64*128 = 8192 threads; 4 threads per batch element

__device__ float g_Cpart[GBLK * 9];
__device__ float g_Spart[GBLK];
__device__ int   g_ctr;      // monotonic barrier ticket counter (never reset)

__device__ __forceinline__ float rcpa(float v) {
    float r; asm("rcp.approx.f32 %0, %1;" : "=f"(r) : "f"(v)); return r;
}
__device__ __forceinline__ float lg2a(float v) {
    float r; asm("lg2.approx.f32 %0, %1;" : "=f"(r) : "f"(v)); return r;
}
__device__ __forceinline__ float ex2a(float v) {
    float r; asm("ex2.approx.f32 %0, %1;" : "=f"(r) : "f"(v)); return r;
}

// (1 + t), t = ((x-c)/a)^(2b), replicating numpy edge cases:
//   b==0        -> t=1   (0**0 == inf**0 == 1)
//   x2==0, b>0  -> t=0
//   a==0        -> x2=inf -> t=inf (product -> inf -> P=0 via rcp)
__device__ __forceinline__ float one_plus_t(float x, float a, float b, float c) {
    float u  = (x - c) * rcpa(a);
    float x2 = u * u;
    float t;
    if (b == 0.0f)       t = 1.0f;
    else if (x2 == 0.0f) t = 0.0f;
    else                 t = ex2a(b * lg2a(x2));
    return 1.0f + t;
}

__global__ __launch_bounds__(TBLK)
void anfis_fused(const float* __restrict__ inp,
                 const float* __restrict__ prem,
                 const float* __restrict__ conseq,
                 float* __restrict__ out) {
    __shared__ float swC[4][9];      // per-warp conseq partials
    __shared__ float swS[4];         // per-warp S partials
    __shared__ float sF[8][9];       // fold level-1
    __shared__ float sS[8];
    __shared__ float sC[9];
    __shared__ float sInvZ;

    const int tid  = threadIdx.x;
    const int bi   = blockIdx.x;
    const int w    = tid >> 5, lane = tid & 31;
    const int quarter = lane >> 3;                 // var pair (0..3)
    const int b    = bi * 32 + w * 8 + (lane & 7); // batch element

    // ---- Issue all global loads up front (MLP overlaps MUFU below) ----
    // Tail group 6560: loaded by every block, folded after the barrier.
    const float tailv = (tid < 9) ? __ldg(conseq + 36 * NQUAD + tid) : 0.0f;

    // Conseq quads on lanes 24..31 of every warp, warp-interleaved for balance.
    float4 cv[9];
    const int qidx = (lane - 24) * 4 + w;          // 0..31 for lanes 24..31
    const int q    = bi + GBLK * qidx;
    const bool qact = (lane >= 24) && (qidx < 26) && (q < NQUAD);
    if (qact) {
        const float4* p = (const float4*)(conseq + 36 * q);
#pragma unroll
        for (int m = 0; m < 9; m++) cv[m] = __ldg(p + m);
    }

    const int i0 = 2 * quarter;                    // this thread's two vars
    const float x0 = __ldg(inp + i0 * NBATCH + b);
    const float x1 = __ldg(inp + (i0 + 1) * NBATCH + b);

    // 18 premise floats (rows 3*i0 .. 3*i0+5) as 9 float2 loads (8B aligned)
    const float2* pr = (const float2*)(prem + 18 * quarter);
    float pp[18];
#pragma unroll
    for (int m = 0; m < 9; m++) {
        float2 v = __ldg(pr + m);
        pp[2 * m] = v.x; pp[2 * m + 1] = v.y;
    }

    // ---- Memberships: 2 vars x 3 sets per thread ----
    float q0 = one_plus_t(x0, pp[0], pp[1], pp[2]) * one_plus_t(x1, pp[9],  pp[10], pp[11]);
    float q1 = one_plus_t(x0, pp[3], pp[4], pp[5]) * one_plus_t(x1, pp[12], pp[13], pp[14]);
    float q2 = one_plus_t(x0, pp[6], pp[7], pp[8]) * one_plus_t(x1, pp[15], pp[16], pp[17]);

    // combine the 4 quarter-lanes (lane bits 3,4)
    q0 *= __shfl_xor_sync(0xffffffffu, q0, 8);
    q1 *= __shfl_xor_sync(0xffffffffu, q1, 8);
    q2 *= __shfl_xor_sync(0xffffffffu, q2, 8);
    q0 *= __shfl_xor_sync(0xffffffffu, q0, 16);
    q1 *= __shfl_xor_sync(0xffffffffu, q1, 16);
    q2 *= __shfl_xor_sync(0xffffffffu, q2, 16);
    const float P0 = rcpa(q0);
    float S = P0 + rcpa(q1) + rcpa(q2);

    // warp S sum over the 8 distinct elements (lane bits 0..2 only —
    // quarter-copies in bits 3,4 are never summed, so no over-count)
    S += __shfl_xor_sync(0xffffffffu, S, 1);
    S += __shfl_xor_sync(0xffffffffu, S, 2);
    S += __shfl_xor_sync(0xffffffffu, S, 4);

    // ---- Accumulate conseq quad into Ctot[9] buckets ----
    float acc[9];
#pragma unroll
    for (int v = 0; v < 9; v++) acc[v] = 0.0f;
    if (qact) {
#pragma unroll
        for (int m = 0; m < 9; m++) {
            acc[(4 * m + 0) % 9] += cv[m].x;
            acc[(4 * m + 1) % 9] += cv[m].y;
            acc[(4 * m + 2) % 9] += cv[m].z;
            acc[(4 * m + 3) % 9] += cv[m].w;
        }
    }
    // butterfly over lanes 24..31 (bits 0..2; inactive lanes hold zeros)
#pragma unroll
    for (int v = 0; v < 9; v++) {
        acc[v] += __shfl_xor_sync(0xffffffffu, acc[v], 1);
        acc[v] += __shfl_xor_sync(0xffffffffu, acc[v], 2);
        acc[v] += __shfl_xor_sync(0xffffffffu, acc[v], 4);
    }
    if (lane >= 24) swC[w][lane - 24] = acc[lane - 24];
    if (lane == 24) swC[w][8] = acc[8];
    if (lane == 0)  swS[w] = S;
    __syncthreads();

    // ---- Parallel publish of this block's partials ----
    if (tid < 9)
        g_Cpart[bi * 9 + tid] = swC[0][tid] + swC[1][tid] + swC[2][tid] + swC[3][tid];
    if (tid == 9)
        g_Spart[bi] = swS[0] + swS[1] + swS[2] + swS[3];
    __syncthreads();

    // ---- Grid barrier (monotonic ticket, graph-replay safe) ----
    if (tid == 0) {
        __threadfence();                           // publishes -> L2 before ticket
        int ticket = atomicAdd(&g_ctr, 1);
        int target = (ticket / GBLK + 1) * GBLK;
        volatile int* vp = &g_ctr;
        while (*vp < target) { }
    }
    __syncthreads();

    // ---- Two-level fold of partials (L2 reads, bypass L1) ----
    if (tid < 72) {                                // 8 parts x 9 buckets
        const int v = tid % 9, part = tid / 9;
        float s = 0.0f;
#pragma unroll
        for (int k = 0; k < GBLK / 8; k++)
            s += __ldcg(&g_Cpart[(part * (GBLK / 8) + k) * 9 + v]);
        sF[part][v] = s;
    }
    if (tid >= 72 && tid < 80) {                   // 8 parts of S
        const int part = tid - 72;
        float s = 0.0f;
#pragma unroll
        for (int k = 0; k < GBLK / 8; k++)
            s += __ldcg(&g_Spart[part * (GBLK / 8) + k]);
        sS[part] = s;
    }
    __syncthreads();
    if (tid < 9) {
        float s = tailv;                           // group 6560 folded here
#pragma unroll
        for (int p = 0; p < 8; p++) s += sF[p][tid];
        sC[tid] = s;
    }
    if (tid == 9) {
        float s = 0.0f;
#pragma unroll
        for (int p = 0; p < 8; p++) s += sS[p];
        sInvZ = 1.0f / (2187.0f * s);              // Z = 2187 * sum_b (P0+P1+P2)
    }
    __syncthreads();

    // ---- Finalize: dot via butterfly over the 4 quarter-lanes ----
    float d = x0 * sC[i0] + x1 * sC[i0 + 1];
    d += __shfl_xor_sync(0xffffffffu, d, 8);
    d += __shfl_xor_sync(0xffffffffu, d, 16);
    if (quarter == 0)
        out[b] = P0 * (d + sC[8]) * sInvZ;
}

extern "C" void kernel_launch(void* const* d_in, const int* in_sizes, int n_in,
                              void* d_out, int out_size) {
    const float* inp    = (const float*)d_in[0];   // (8, 2048)
    const float* prem   = (const float*)d_in[1];   // (24, 3)
    const float* conseq = (const float*)d_in[2];   // (59049, 1)
    float* out = (float*)d_out;                    // (2048, 1)

    anfis_fused<<<GBLK, TBLK>>>(inp, prem, conseq, out);
}

// round 11
// speedup vs baseline: 1.2161x; 1.0256x over previous
#include <cuda_runtime.h>

#define NBATCH 2048
#define NVAR   8
#define NTOT   6561          // 3^8
#define NQUAD  1640          // full 4-group (144B) quads; group 6560 is the tail
#define GBLK   64
#define TBLK   128           // 64*128 = 8192 threads; 4 threads per batch element

__device__ float g_Cpart[9][GBLK]; // bucket-major: fold reads are contiguous
__device__ float g_Spart[GBLK];
__device__ int   g_ctr;            // monotonic barrier counter (never reset)

__device__ __forceinline__ float rcpa(float v) {
    float r; asm("rcp.approx.f32 %0, %1;" : "=f"(r) : "f"(v)); return r;
}
__device__ __forceinline__ float lg2a(float v) {
    float r; asm("lg2.approx.f32 %0, %1;" : "=f"(r) : "f"(v)); return r;
}
__device__ __forceinline__ float ex2a(float v) {
    float r; asm("ex2.approx.f32 %0, %1;" : "=f"(r) : "f"(v)); return r;
}
__device__ __forceinline__ int ld_acq(const int* p) {
    int v; asm volatile("ld.acquire.gpu.global.u32 %0, [%1];" : "=r"(v) : "l"(p) : "memory");
    return v;
}

// (1 + t), t = ((x-c)/a)^(2b), replicating numpy edge cases:
//   b==0        -> t=1   (0**0 == inf**0 == 1)
//   x2==0, b>0  -> t=0
//   a==0        -> x2=inf -> t=inf (product -> inf -> P=0 via rcp)
__device__ __forceinline__ float one_plus_t(float x, float a, float b, float c) {
    float u  = (x - c) * rcpa(a);
    float x2 = u * u;
    float t;
    if (b == 0.0f)       t = 1.0f;
    else if (x2 == 0.0f) t = 0.0f;
    else                 t = ex2a(b * lg2a(x2));
    return 1.0f + t;
}

__global__ __launch_bounds__(TBLK)
void anfis_fused(const float* __restrict__ inp,
                 const float* __restrict__ prem,
                 const float* __restrict__ conseq,
                 float* __restrict__ out) {
    __shared__ float swC[4][9];      // per-warp conseq partials
    __shared__ float swS[4];         // per-warp S partials
    __shared__ float sF[8][9];       // fold level-1
    __shared__ float sS[8];
    __shared__ float sC[9];
    __shared__ float sInvZ;
    __shared__ int   sDone;          // spin-exit flag (reset every launch)

    const int tid  = threadIdx.x;
    const int bi   = blockIdx.x;
    const int w    = tid >> 5, lane = tid & 31;
    const int quarter = lane >> 3;                 // var pair (0..3)
    const int b    = bi * 32 + w * 8 + (lane & 7); // batch element

    // ---- Issue all global loads up front (latency hidden under MUFU) ----
    // Early epoch read: target = (r/GBLK+1)*GBLK is invariant for any r read
    // during this launch's epoch of the monotonic counter.
    int ectr = 0;
    if (tid < 4) ectr = __ldcg(&g_ctr);
    if (tid == 10) sDone = 0;

    // Tail group 6560: loaded by every block, folded after the barrier.
    const float tailv = (tid < 9) ? __ldg(conseq + 36 * NQUAD + tid) : 0.0f;

    // Conseq quads on lanes 24..31 of every warp, warp-interleaved for balance.
    float4 cv[9];
    const int qidx = (lane - 24) * 4 + w;          // 0..31 for lanes 24..31
    const int q    = bi + GBLK * qidx;
    const bool qact = (lane >= 24) && (qidx < 26) && (q < NQUAD);
    if (qact) {
        const float4* p = (const float4*)(conseq + 36 * q);
#pragma unroll
        for (int m = 0; m < 9; m++) cv[m] = __ldg(p + m);
    }

    const int i0 = 2 * quarter;                    // this thread's two vars
    const float x0 = __ldg(inp + i0 * NBATCH + b);
    const float x1 = __ldg(inp + (i0 + 1) * NBATCH + b);

    // 18 premise floats (rows 3*i0 .. 3*i0+5) as 9 float2 loads (8B aligned)
    const float2* pr = (const float2*)(prem + 18 * quarter);
    float pp[18];
#pragma unroll
    for (int m = 0; m < 9; m++) {
        float2 v = __ldg(pr + m);
        pp[2 * m] = v.x; pp[2 * m + 1] = v.y;
    }

    // ---- Memberships: 2 vars x 3 sets per thread ----
    float q0 = one_plus_t(x0, pp[0], pp[1], pp[2]) * one_plus_t(x1, pp[9],  pp[10], pp[11]);
    float q1 = one_plus_t(x0, pp[3], pp[4], pp[5]) * one_plus_t(x1, pp[12], pp[13], pp[14]);
    float q2 = one_plus_t(x0, pp[6], pp[7], pp[8]) * one_plus_t(x1, pp[15], pp[16], pp[17]);

    // combine the 4 quarter-lanes (lane bits 3,4)
    q0 *= __shfl_xor_sync(0xffffffffu, q0, 8);
    q1 *= __shfl_xor_sync(0xffffffffu, q1, 8);
    q2 *= __shfl_xor_sync(0xffffffffu, q2, 8);
    q0 *= __shfl_xor_sync(0xffffffffu, q0, 16);
    q1 *= __shfl_xor_sync(0xffffffffu, q1, 16);
    q2 *= __shfl_xor_sync(0xffffffffu, q2, 16);
    const float P0 = rcpa(q0);
    float S = P0 + rcpa(q1) + rcpa(q2);

    // warp S sum over the 8 distinct elements (lane bits 0..2 only)
    S += __shfl_xor_sync(0xffffffffu, S, 1);
    S += __shfl_xor_sync(0xffffffffu, S, 2);
    S += __shfl_xor_sync(0xffffffffu, S, 4);

    // ---- Accumulate conseq quad into Ctot[9] buckets ----
    float acc[9];
#pragma unroll
    for (int v = 0; v < 9; v++) acc[v] = 0.0f;
    if (qact) {
#pragma unroll
        for (int m = 0; m < 9; m++) {
            acc[(4 * m + 0) % 9] += cv[m].x;
            acc[(4 * m + 1) % 9] += cv[m].y;
            acc[(4 * m + 2) % 9] += cv[m].z;
            acc[(4 * m + 3) % 9] += cv[m].w;
        }
    }
    // butterfly over lanes 24..31 (bits 0..2; inactive lanes hold zeros)
#pragma unroll
    for (int v = 0; v < 9; v++) {
        acc[v] += __shfl_xor_sync(0xffffffffu, acc[v], 1);
        acc[v] += __shfl_xor_sync(0xffffffffu, acc[v], 2);
        acc[v] += __shfl_xor_sync(0xffffffffu, acc[v], 4);
    }
    if (lane >= 24) swC[w][lane - 24] = acc[lane - 24];
    if (lane == 24) swC[w][8] = acc[8];
    if (lane == 0)  swS[w] = S;
    __syncthreads();

    // ---- Parallel publish of this block's partials (bucket-major) ----
    if (tid < 9)
        g_Cpart[tid][bi] = swC[0][tid] + swC[1][tid] + swC[2][tid] + swC[3][tid];
    if (tid == 9)
        g_Spart[bi] = swS[0] + swS[1] + swS[2] + swS[3];
    __syncthreads();

    // ---- Grid barrier: fire-and-forget red + 4 staggered spinners ----
    if (tid == 0) {
        __threadfence();                           // publishes -> L2 before red
        asm volatile("red.global.add.u32 [%0], %1;" :: "l"(&g_ctr), "r"(1) : "memory");
    }
    if (tid < 4) {
        const int target = (ectr / GBLK + 1) * GBLK;
        volatile int* vd = &sDone;
        while (true) {
            if (*vd) break;
            if (ld_acq(&g_ctr) >= target) { *vd = 1; break; }
        }
    }
    __syncthreads();

    // ---- Two-level fold of partials (vectorized L2 reads) ----
    if (tid < 72) {                                // 9 buckets x 8 parts
        const int v = tid >> 3, part = tid & 7;
        const float4* p = (const float4*)&g_Cpart[v][part * 8];
        float4 u0 = __ldcg(p), u1 = __ldcg(p + 1);
        sF[part][v] = ((u0.x + u0.y) + (u0.z + u0.w))
                    + ((u1.x + u1.y) + (u1.z + u1.w));
    }
    if (tid >= 72 && tid < 80) {                   // 8 parts of S
        const int part = tid - 72;
        const float4* p = (const float4*)&g_Spart[part * 8];
        float4 u0 = __ldcg(p), u1 = __ldcg(p + 1);
        sS[part] = ((u0.x + u0.y) + (u0.z + u0.w))
                 + ((u1.x + u1.y) + (u1.z + u1.w));
    }
    __syncthreads();
    if (tid < 9) {
        float s = tailv;                           // group 6560 folded here
#pragma unroll
        for (int p = 0; p < 8; p++) s += sF[p][tid];
        sC[tid] = s;
    }
    if (tid == 9) {
        float s = 0.0f;
#pragma unroll
        for (int p = 0; p < 8; p++) s += sS[p];
        sInvZ = 1.0f / (2187.0f * s);              // Z = 2187 * sum_b (P0+P1+P2)
    }
    __syncthreads();

    // ---- Finalize: dot via butterfly over the 4 quarter-lanes ----
    float d = x0 * sC[i0] + x1 * sC[i0 + 1];
    d += __shfl_xor_sync(0xffffffffu, d, 8);
    d += __shfl_xor_sync(0xffffffffu, d, 16);
    if (quarter == 0)
        out[b] = P0 * (d + sC[8]) * sInvZ;
}

extern "C" void kernel_launch(void* const* d_in, const int* in_sizes, int n_in,
                              void* d_out, int out_size) {
    const float* inp    = (const float*)d_in[0];   // (8, 2048)
    const float* prem   = (const float*)d_in[1];   // (24, 3)
    const float* conseq = (const float*)d_in[2];   // (59049, 1)
    float* out = (float*)d_out;                    // (2048, 1)

    anfis_fused<<<GBLK, TBLK>>>(inp, prem, conseq, out);
}

// round 13
// speedup vs baseline: 1.2251x; 1.0074x over previous
#include <cuda_runtime.h>

#define NBATCH 2048
#define NVAR   8
#define NTOT   6561          // 3^8
#define NQUAD  1640          // full 4-group (144B) quads; group 6560 is the tail
#define GBLK   64
#define TBLK   128           // 64*128 = 8192 threads; 4 threads per batch element
#define NPART  (GBLK * 4)    // per-WARP partials now: 256

__device__ float g_Cpart[9][NPART]; // bucket-major: fold reads contiguous
__device__ float g_Spart[NPART];
__device__ int   g_ctr;             // monotonic barrier counter (never reset)

__device__ __forceinline__ float rcpa(float v) {
    float r; asm("rcp.approx.f32 %0, %1;" : "=f"(r) : "f"(v)); return r;
}
__device__ __forceinline__ float lg2a(float v) {
    float r; asm("lg2.approx.f32 %0, %1;" : "=f"(r) : "f"(v)); return r;
}
__device__ __forceinline__ float ex2a(float v) {
    float r; asm("ex2.approx.f32 %0, %1;" : "=f"(r) : "f"(v)); return r;
}
__device__ __forceinline__ int ld_acq(const int* p) {
    int v; asm volatile("ld.acquire.gpu.global.u32 %0, [%1];" : "=r"(v) : "l"(p) : "memory");
    return v;
}

// (1+t), t = ((x-c)/a)^(2b) via log form: t = ex2(b*lg2((x-c)^2) - K),
// K = b*lg2(a^2). Edge cases vs numpy:
//   b==0              -> t=1 (explicit guard; 0**0 == inf**0 == 1)
//   x2==0, b>0        -> lg2=-inf -> e=-inf -> t=0   (automatic)
//   a==0, b>0         -> K=-inf   -> e=+inf -> t=inf (automatic; P -> 0)
__device__ __forceinline__ float one_plus_t(float x, float b, float c, float K) {
    float d  = x - c;
    float x2 = d * d;
    float t  = ex2a(fmaf(b, lg2a(x2), -K));
    if (b == 0.0f) t = 1.0f;
    return 1.0f + t;
}

__global__ __launch_bounds__(TBLK)
void anfis_fused(const float* __restrict__ inp,
                 const float* __restrict__ prem,
                 const float* __restrict__ conseq,
                 float* __restrict__ out) {
    __shared__ float sF[8][9];       // fold level-1
    __shared__ float sS[8];
    __shared__ float sC[9];
    __shared__ float sInvZ;
    __shared__ int   sDone;          // spin-exit flag (reset every launch)

    const int tid  = threadIdx.x;
    const int bi   = blockIdx.x;
    const int w    = tid >> 5, lane = tid & 31;
    const int quarter = lane >> 3;                 // var pair (0..3)
    const int j    = lane & 7;                     // role within 8-lane group
    const int b    = bi * 32 + w * 8 + j;          // batch element

    // ---- Issue all global loads up front (latency hidden under MUFU) ----
    // Early epoch read: target = (r/GBLK+1)*GBLK is invariant for any r read
    // during this launch's epoch of the monotonic counter.
    int ectr = 0;
    if (tid < 4) ectr = __ldcg(&g_ctr);
    if (tid == 10) sDone = 0;

    // Tail group 6560: loaded by every block, folded after the barrier.
    const float tailv = (tid < 9) ? __ldg(conseq + 36 * NQUAD + tid) : 0.0f;

    // Conseq quads on lanes 24..31 of every warp, warp-interleaved for balance.
    float4 cv[9];
    const int qidx = (lane - 24) * 4 + w;          // 0..31 for lanes 24..31
    const int q    = bi + GBLK * qidx;
    const bool qact = (lane >= 24) && (qidx < 26) && (q < NQUAD);
    if (qact) {
        const float4* p = (const float4*)(conseq + 36 * q);
#pragma unroll
        for (int m = 0; m < 9; m++) cv[m] = __ldg(p + m);
    }

    const int i0 = 2 * quarter;                    // this thread's two vars
    const float x0 = __ldg(inp + i0 * NBATCH + b);
    const float x1 = __ldg(inp + (i0 + 1) * NBATCH + b);

    // 18 premise floats (rows 3*i0 .. 3*i0+5) as 9 float2 loads (8B aligned)
    const float2* pr = (const float2*)(prem + 18 * quarter);
    float pp[18];
#pragma unroll
    for (int m = 0; m < 9; m++) {
        float2 v = __ldg(pr + m);
        pp[2 * m] = v.x; pp[2 * m + 1] = v.y;
    }

    // ---- K constants: lane j<6 of each group computes K_j = b_j*lg2(a_j^2) ----
    float Kv = 0.0f;
    if (j < 6) {
        const float aj = __ldg(prem + 18 * quarter + 3 * j);
        const float bj = __ldg(prem + 18 * quarter + 3 * j + 1);
        Kv = bj * 2.0f * lg2a(fabsf(aj));
    }
    const int gb = lane & 24;
    const float K0 = __shfl_sync(0xffffffffu, Kv, gb + 0);
    const float K1 = __shfl_sync(0xffffffffu, Kv, gb + 1);
    const float K2 = __shfl_sync(0xffffffffu, Kv, gb + 2);
    const float K3 = __shfl_sync(0xffffffffu, Kv, gb + 3);
    const float K4 = __shfl_sync(0xffffffffu, Kv, gb + 4);
    const float K5 = __shfl_sync(0xffffffffu, Kv, gb + 5);

    // ---- Memberships: 2 vars x 3 sets per thread (12 MUFU) ----
    float q0 = one_plus_t(x0, pp[1],  pp[2],  K0) * one_plus_t(x1, pp[10], pp[11], K3);
    float q1 = one_plus_t(x0, pp[4],  pp[5],  K1) * one_plus_t(x1, pp[13], pp[14], K4);
    float q2 = one_plus_t(x0, pp[7],  pp[8],  K2) * one_plus_t(x1, pp[16], pp[17], K5);

    // combine the 4 quarter-lanes (lane bits 3,4)
    q0 *= __shfl_xor_sync(0xffffffffu, q0, 8);
    q1 *= __shfl_xor_sync(0xffffffffu, q1, 8);
    q2 *= __shfl_xor_sync(0xffffffffu, q2, 8);
    q0 *= __shfl_xor_sync(0xffffffffu, q0, 16);
    q1 *= __shfl_xor_sync(0xffffffffu, q1, 16);
    q2 *= __shfl_xor_sync(0xffffffffu, q2, 16);
    const float P0 = rcpa(q0);
    float S = P0 + rcpa(q1) + rcpa(q2);

    // warp S sum over the 8 distinct elements (lane bits 0..2 only)
    S += __shfl_xor_sync(0xffffffffu, S, 1);
    S += __shfl_xor_sync(0xffffffffu, S, 2);
    S += __shfl_xor_sync(0xffffffffu, S, 4);

    // ---- Accumulate conseq quad into Ctot[9] buckets ----
    float acc[9];
#pragma unroll
    for (int v = 0; v < 9; v++) acc[v] = 0.0f;
    if (qact) {
#pragma unroll
        for (int m = 0; m < 9; m++) {
            acc[(4 * m + 0) % 9] += cv[m].x;
            acc[(4 * m + 1) % 9] += cv[m].y;
            acc[(4 * m + 2) % 9] += cv[m].z;
            acc[(4 * m + 3) % 9] += cv[m].w;
        }
    }
    // butterfly over lanes 24..31 (bits 0..2; inactive lanes hold zeros)
#pragma unroll
    for (int v = 0; v < 9; v++) {
        acc[v] += __shfl_xor_sync(0xffffffffu, acc[v], 1);
        acc[v] += __shfl_xor_sync(0xffffffffu, acc[v], 2);
        acc[v] += __shfl_xor_sync(0xffffffffu, acc[v], 4);
    }

    // ---- Direct per-warp publish (no block-level combine) ----
    const int part = bi * 4 + w;
    if (lane >= 24) g_Cpart[lane - 24][part] = acc[lane - 24];
    if (lane == 24) g_Cpart[8][part] = acc[8];
    if (lane == 0)  g_Spart[part] = S;
    __syncthreads();

    // ---- Grid barrier: release-red, then spin ----
    if (tid == 0)
        asm volatile("red.release.gpu.global.add.u32 [%0], %1;"
                     :: "l"(&g_ctr), "r"(1) : "memory");
    if (tid < 4) {
        const int target = (ectr / GBLK + 1) * GBLK;
        volatile int* vd = &sDone;
        while (true) {
            if (*vd) break;
            if (ld_acq(&g_ctr) >= target) { *vd = 1; break; }
        }
    }
    __syncthreads();

    // ---- Two-level fold of 256 partials (vectorized L2 reads) ----
    if (tid < 72) {                                // 9 buckets x 8 parts of 32
        const int v = tid >> 3, pt = tid & 7;
        const float4* p = (const float4*)&g_Cpart[v][pt * 32];
        float s = 0.0f;
#pragma unroll
        for (int k = 0; k < 8; k++) {
            float4 u = __ldcg(p + k);
            s += (u.x + u.y) + (u.z + u.w);
        }
        sF[pt][v] = s;
    }
    if (tid >= 72 && tid < 80) {                   // 8 parts of S (32 each)
        const int pt = tid - 72;
        const float4* p = (const float4*)&g_Spart[pt * 32];
        float s = 0.0f;
#pragma unroll
        for (int k = 0; k < 8; k++) {
            float4 u = __ldcg(p + k);
            s += (u.x + u.y) + (u.z + u.w);
        }
        sS[pt] = s;
    }
    __syncthreads();
    if (tid < 9) {
        float s = tailv;                           // group 6560 folded here
#pragma unroll
        for (int p = 0; p < 8; p++) s += sF[p][tid];
        sC[tid] = s;
    }
    if (tid == 9) {
        float s = 0.0f;
#pragma unroll
        for (int p = 0; p < 8; p++) s += sS[p];
        sInvZ = 1.0f / (2187.0f * s);              // Z = 2187 * sum_b (P0+P1+P2)
    }
    __syncthreads();

    // ---- Finalize: dot via butterfly over the 4 quarter-lanes ----
    float d = x0 * sC[i0] + x1 * sC[i0 + 1];
    d += __shfl_xor_sync(0xffffffffu, d, 8);
    d += __shfl_xor_sync(0xffffffffu, d, 16);
    if (quarter == 0)
        out[b] = P0 * (d + sC[8]) * sInvZ;
}

extern "C" void kernel_launch(void* const* d_in, const int* in_sizes, int n_in,
                              void* d_out, int out_size) {
    const float* inp    = (const float*)d_in[0];   // (8, 2048)
    const float* prem   = (const float*)d_in[1];   // (24, 3)
    const float* conseq = (const float*)d_in[2];   // (59049, 1)
    float* out = (float*)d_out;                    // (2048, 1)

    anfis_fused<<<GBLK, TBLK>>>(inp, prem, conseq, out);
}